// round 5
// baseline (speedup 1.0000x reference)
#include <cuda_runtime.h>
#include <math.h>

#define NPTS 32768
#define CIN  32
#define F0   256
#define KATT 1024
#define BSEG 16
#define KC   32768
#define EPAD 40
#define BN_EPS 1e-5f

#define TILE_N 256
#define SATT 260            /* floats, stride of resident att / sE tile   */
#define SXS  40             /* floats, stride of x_aug tile               */
#define SBS  36             /* floats, stride of B-operand staging        */
#define ATT_OFF 0
#define SX_OFF  (128 * SATT)                 /* 33280 */
#define SW_OFF  (SX_OFF + 128 * SXS)         /* 38400 */
#define SB_STAGE (256 * SBS)                 /* 9216 floats per stage */
#define SMEM_FLOATS (SW_OFF + 2 * SB_STAGE)  /* 56832 -> 227328 B */

// ---------------- scratch ----------------
__device__ float g_E[BSEG * KATT * EPAD];
__device__ float g_out2[BSEG * KC];
__device__ float g_rtmp[BSEG * F0];
__device__ float g_s1[F0], g_t1[F0];
__device__ float g_s2[KATT], g_t2[KATT];
__device__ float g_s3[F0], g_t3[F0];
__device__ int   g_off[BSEG + 1];

// ---------------- helpers ----------------
static __device__ __forceinline__ unsigned utf32(float x) {
    unsigned r;
    asm("cvt.rna.tf32.f32 %0, %1;" : "=r"(r) : "f"(x));
    return r;
}

static __device__ __forceinline__ void mma_tf32(float* d, const unsigned* a, const unsigned* b) {
    asm volatile(
        "mma.sync.aligned.m16n8k8.row.col.f32.tf32.tf32.f32 "
        "{%0,%1,%2,%3}, {%4,%5,%6,%7}, {%8,%9}, {%0,%1,%2,%3};\n"
        : "+f"(d[0]), "+f"(d[1]), "+f"(d[2]), "+f"(d[3])
        : "r"(a[0]), "r"(a[1]), "r"(a[2]), "r"(a[3]), "r"(b[0]), "r"(b[1]));
}

static __device__ __forceinline__ void cpa16(unsigned* s, const float* g) {
    unsigned sa = (unsigned)__cvta_generic_to_shared(s);
    asm volatile("cp.async.cg.shared.global [%0], [%1], 16;\n" :: "r"(sa), "l"(g));
}
#define CPA_COMMIT() asm volatile("cp.async.commit_group;\n" ::: "memory")
#define CPA_WAIT0()  asm volatile("cp.async.wait_group 0;\n" ::: "memory")

static __device__ __forceinline__ int seg_of(int row) {
    int s = 0;
    while (s < BSEG - 1 && row >= g_off[s + 1]) s++;
    return s;
}

// ---------------- k0 ----------------
__global__ void k0_prep(const int* __restrict__ len,
                        const float* __restrict__ b1, const float* __restrict__ g1,
                        const float* __restrict__ be1, const float* __restrict__ m1,
                        const float* __restrict__ v1,
                        const float* __restrict__ b2, const float* __restrict__ g2,
                        const float* __restrict__ be2, const float* __restrict__ m2,
                        const float* __restrict__ v2,
                        const float* __restrict__ fcb, const float* __restrict__ g3,
                        const float* __restrict__ be3, const float* __restrict__ m3,
                        const float* __restrict__ v3) {
    int t = threadIdx.x;
    if (t == 0) {
        int acc = 0;
        for (int i = 0; i < BSEG; i++) { g_off[i] = acc; acc += len[i]; }
        g_off[BSEG] = acc;
    }
    if (t < F0) {
        float a = g1[t] * rsqrtf(v1[t] + BN_EPS);
        g_s1[t] = a;
        g_t1[t] = (b1[t] - m1[t]) * a + be1[t];
        float a3 = g3[t] * rsqrtf(v3[t] + BN_EPS);
        g_s3[t] = a3;
        g_t3[t] = (fcb[t] - m3[t]) * a3 + be3[t];
    }
    {
        float a2 = g2[t] * rsqrtf(v2[t] + BN_EPS);
        g_s2[t] = a2;
        g_t2[t] = (b2[t] - m2[t]) * a2 + be2[t];
    }
}

__global__ void k0_zero() {
    int idx = blockIdx.x * 256 + threadIdx.x;
    if (idx < BSEG * KATT * EPAD) g_E[idx] = 0.f;
    if (idx < BSEG * F0) g_rtmp[idx] = 0.f;
}

// ---------------- k2: fully fused  x -> att1 -> att2 -> exp -> pooled E ----------------
// 1 CTA/SM, 256 threads, 8 warps in 2x4 grid of 64x64 warp tiles.
__global__ __launch_bounds__(256, 1) void k2_main(const float* __restrict__ x,
                                                  const float* __restrict__ w1,
                                                  const float* __restrict__ w2) {
    extern __shared__ unsigned sm[];
    unsigned* sAtt = sm + ATT_OFF;   // [128][260] att tile (tf32-compatible f32 bits)
    unsigned* sX   = sm + SX_OFF;    // [128][40]  x_aug (cols 0-31 x, 32=1, 33-39=0)
    unsigned* sW   = sm + SW_OFF;    // sW1 [256][36]  /  later 2 stages of sB2 [256][36]

    int tid = threadIdx.x;
    int rowBase = blockIdx.x * 128;
    int colBase = blockIdx.y * TILE_N;
    int wid = tid >> 5, lane = tid & 31;
    int g = lane >> 2, tg = lane & 3;
    int wr = (wid & 1) * 64;          // warp row offset  (2)
    int wc = (wid >> 1) * 64;         // warp col offset  (4)

    float acc[4][8][4];

    // ---- stage x tile (128x32) and w1 (256x32) ----
#pragma unroll
    for (int i = 0; i < 4; i++) {
        int u = tid + i * 256;        // 0..1023
        int r = u >> 3, cu = u & 7;
        cpa16(sX + r * SXS + cu * 4, x + (long)(rowBase + r) * CIN + cu * 4);
    }
#pragma unroll
    for (int i = 0; i < 8; i++) {
        int u = tid + i * 256;        // 0..2047
        int r = u >> 3, cu = u & 7;
        cpa16(sW + r * SBS + cu * 4, w1 + (long)r * CIN + cu * 4);
    }
    CPA_COMMIT();
    CPA_WAIT0();
    __syncthreads();

    // x_aug extension cols 32..39
#pragma unroll
    for (int i = 0; i < 4; i++) {
        int u = tid + i * 256;        // 0..1023 -> 128 rows x 8 cols
        int r = u >> 3, cx = 32 + (u & 7);
        ((float*)sX)[r * SXS + cx] = (cx == 32) ? 1.0f : 0.0f;
    }

    // ---- GEMM1: att = relu(bn1(x @ w1^T)), 128x256, K=32 ----
#pragma unroll
    for (int mt = 0; mt < 4; mt++)
#pragma unroll
        for (int nt = 0; nt < 8; nt++)
#pragma unroll
            for (int q = 0; q < 4; q++) acc[mt][nt][q] = 0.f;

#pragma unroll
    for (int ks = 0; ks < 32; ks += 8) {
        unsigned af[4][4], bf[8][2];
#pragma unroll
        for (int mt = 0; mt < 4; mt++) {
            int r0 = wr + mt * 16 + g;
            af[mt][0] = sX[r0 * SXS + ks + tg];
            af[mt][1] = sX[(r0 + 8) * SXS + ks + tg];
            af[mt][2] = sX[r0 * SXS + ks + tg + 4];
            af[mt][3] = sX[(r0 + 8) * SXS + ks + tg + 4];
        }
#pragma unroll
        for (int nt = 0; nt < 8; nt++) {
            int n0 = wc + nt * 8 + g;
            bf[nt][0] = sW[n0 * SBS + ks + tg];
            bf[nt][1] = sW[n0 * SBS + ks + tg + 4];
        }
#pragma unroll
        for (int mt = 0; mt < 4; mt++)
#pragma unroll
            for (int nt = 0; nt < 8; nt++) mma_tf32(acc[mt][nt], af[mt], bf[nt]);
    }

    // bn1 + relu -> sAtt (raw f32 bits; tf32 truncation happens in mma HW)
#pragma unroll
    for (int mt = 0; mt < 4; mt++) {
#pragma unroll
        for (int nt = 0; nt < 8; nt++) {
            int col = wc + nt * 8 + 2 * tg;
            float s0 = g_s1[col], t0 = g_t1[col];
            float s1v = g_s1[col + 1], t1v = g_t1[col + 1];
            int r0 = wr + mt * 16 + g;
            float v0 = fmaxf(acc[mt][nt][0] * s0 + t0, 0.f);
            float v1 = fmaxf(acc[mt][nt][1] * s1v + t1v, 0.f);
            float v2 = fmaxf(acc[mt][nt][2] * s0 + t0, 0.f);
            float v3 = fmaxf(acc[mt][nt][3] * s1v + t1v, 0.f);
            *(float2*)&((float*)sAtt)[r0 * SATT + col] = make_float2(v0, v1);
            *(float2*)&((float*)sAtt)[(r0 + 8) * SATT + col] = make_float2(v2, v3);
        }
    }
    __syncthreads();   // att resident; sW region now free for B staging

    // ---- GEMM2 mainloop: att2 = att @ w2^T over this 256-col tile, K=256 ----
#pragma unroll
    for (int mt = 0; mt < 4; mt++)
#pragma unroll
        for (int nt = 0; nt < 8; nt++)
#pragma unroll
            for (int q = 0; q < 4; q++) acc[mt][nt][q] = 0.f;

    const float* gB = w2 + (long)colBase * F0;

    // prologue: stage chunk 0 into stage 0
    {
        unsigned* sB = sW;
#pragma unroll
        for (int i = 0; i < 8; i++) {
            int u = tid + i * 256;
            int r = u >> 3, cu = u & 7;
            cpa16(sB + r * SBS + cu * 4, gB + (long)r * F0 + cu * 4);
        }
        CPA_COMMIT();
    }

    for (int c = 0; c < 8; c++) {
        CPA_WAIT0();
        __syncthreads();   // chunk c visible to all; compute(c-1) done

        if (c + 1 < 8) {
            unsigned* sB = sW + ((c + 1) & 1) * SB_STAGE;
            int kc = (c + 1) * 32;
#pragma unroll
            for (int i = 0; i < 8; i++) {
                int u = tid + i * 256;
                int r = u >> 3, cu = u & 7;
                cpa16(sB + r * SBS + cu * 4, gB + (long)r * F0 + kc + cu * 4);
            }
            CPA_COMMIT();
        }

        unsigned* sB = sW + (c & 1) * SB_STAGE;
        int kc = c * 32;
#pragma unroll
        for (int ks = 0; ks < 32; ks += 8) {
            unsigned af[4][4], bf[8][2];
#pragma unroll
            for (int mt = 0; mt < 4; mt++) {
                int r0 = wr + mt * 16 + g;
                af[mt][0] = sAtt[r0 * SATT + kc + ks + tg];
                af[mt][1] = sAtt[(r0 + 8) * SATT + kc + ks + tg];
                af[mt][2] = sAtt[r0 * SATT + kc + ks + tg + 4];
                af[mt][3] = sAtt[(r0 + 8) * SATT + kc + ks + tg + 4];
            }
#pragma unroll
            for (int nt = 0; nt < 8; nt++) {
                int n0 = wc + nt * 8 + g;
                bf[nt][0] = sB[n0 * SBS + ks + tg];
                bf[nt][1] = sB[n0 * SBS + ks + tg + 4];
            }
#pragma unroll
            for (int mt = 0; mt < 4; mt++)
#pragma unroll
                for (int nt = 0; nt < 8; nt++) mma_tf32(acc[mt][nt], af[mt], bf[nt]);
        }
    }

    __syncthreads();   // all reads of sAtt done; safe to overwrite with sE

    // ---- epilogue: e = exp(relu(bn2(acc))) -> sE (aliases sAtt) ----
    unsigned* sE = sAtt;
#pragma unroll
    for (int mt = 0; mt < 4; mt++) {
#pragma unroll
        for (int nt = 0; nt < 8; nt++) {
            int col = wc + nt * 8 + 2 * tg;
            int colG = colBase + col;
            float s0 = g_s2[colG], t0 = g_t2[colG];
            float s1v = g_s2[colG + 1], t1v = g_t2[colG + 1];
            int r0 = wr + mt * 16 + g;
            float e0 = __expf(fmaxf(acc[mt][nt][0] * s0 + t0, 0.f));
            float e1 = __expf(fmaxf(acc[mt][nt][1] * s1v + t1v, 0.f));
            float e2 = __expf(fmaxf(acc[mt][nt][2] * s0 + t0, 0.f));
            float e3 = __expf(fmaxf(acc[mt][nt][3] * s1v + t1v, 0.f));
            sE[r0 * SATT + col] = utf32(e0);
            sE[r0 * SATT + col + 1] = utf32(e1);
            sE[(r0 + 8) * SATT + col] = utf32(e2);
            sE[(r0 + 8) * SATT + col + 1] = utf32(e3);
        }
    }
    __syncthreads();

    // ---- phase-2: per-segment e^T @ x_aug, 32 att-cols per warp (2 groups of 16) ----
    int s0 = seg_of(rowBase), s1 = seg_of(rowBase + 127);
#pragma unroll
    for (int cg = 0; cg < 2; cg++) {
        int mcol = wid * 32 + cg * 16;
        for (int s = s0; s <= s1; s++) {
            int lo = max(g_off[s] - rowBase, 0);
            int hi = min(g_off[s + 1] - rowBase, 128);
            float ea[5][4] = {};
            for (int kk = (lo & ~7); kk < hi; kk += 8) {
                int r0 = kk + tg, r1 = kk + tg + 4;
                bool m0 = (r0 >= lo && r0 < hi);
                bool m1 = (r1 >= lo && r1 < hi);
                unsigned af[4];
                af[0] = m0 ? sE[r0 * SATT + mcol + g] : 0u;
                af[1] = m0 ? sE[r0 * SATT + mcol + g + 8] : 0u;
                af[2] = m1 ? sE[r1 * SATT + mcol + g] : 0u;
                af[3] = m1 ? sE[r1 * SATT + mcol + g + 8] : 0u;
#pragma unroll
                for (int nt = 0; nt < 5; nt++) {
                    unsigned bf[2];
                    bf[0] = sX[r0 * SXS + nt * 8 + g];
                    bf[1] = sX[r1 * SXS + nt * 8 + g];
                    mma_tf32(ea[nt], af, bf);
                }
            }
#pragma unroll
            for (int nt = 0; nt < 5; nt++) {
                int n = nt * 8 + 2 * tg;
                int ac0 = colBase + mcol + g;
                int ac1 = ac0 + 8;
                if (n <= 32) atomicAdd(&g_E[((long)s * KATT + ac0) * EPAD + n], ea[nt][0]);
                if (n + 1 <= 32) atomicAdd(&g_E[((long)s * KATT + ac0) * EPAD + n + 1], ea[nt][1]);
                if (n <= 32) atomicAdd(&g_E[((long)s * KATT + ac1) * EPAD + n], ea[nt][2]);
                if (n + 1 <= 32) atomicAdd(&g_E[((long)s * KATT + ac1) * EPAD + n + 1], ea[nt][3]);
            }
        }
    }
}

// ---------------- k_out2 ----------------
__global__ void k_out2(const int* __restrict__ len) {
    int idx = blockIdx.x * 256 + threadIdx.x;
    int b = idx >> 15;
    int kc = idx & 32767;
    int k = kc >> 5, c = kc & 31;
    const float* Eb = &g_E[((long)b * KATT + k) * EPAD];
    float S = Eb[32];
    g_out2[idx] = Eb[c] / (S * (float)len[b]);
}

// ---------------- k3 ----------------
__global__ __launch_bounds__(256) void k3_fc(const float* __restrict__ fcw) {
    int wg = blockIdx.x * 8 + (threadIdx.x >> 5);
    int lane = threadIdx.x & 31;
    int jg = wg & 31;
    int slice = wg >> 5;
    int j0 = jg * 8;
    int base = slice * 1024;
    float acc[8][16] = {};
    for (int it = 0; it < 32; it++) {
        int kc = base + it * 32 + lane;
        float w[8];
#pragma unroll
        for (int jj = 0; jj < 8; jj++) w[jj] = fcw[(long)(j0 + jj) * KC + kc];
#pragma unroll
        for (int bb = 0; bb < 16; bb++) {
            float o = g_out2[bb * KC + kc];
#pragma unroll
            for (int jj = 0; jj < 8; jj++) acc[jj][bb] = fmaf(o, w[jj], acc[jj][bb]);
        }
    }
#pragma unroll
    for (int jj = 0; jj < 8; jj++) {
#pragma unroll
        for (int bb = 0; bb < 16; bb++) {
            float v = acc[jj][bb];
            v += __shfl_down_sync(0xffffffffu, v, 16);
            v += __shfl_down_sync(0xffffffffu, v, 8);
            v += __shfl_down_sync(0xffffffffu, v, 4);
            v += __shfl_down_sync(0xffffffffu, v, 2);
            v += __shfl_down_sync(0xffffffffu, v, 1);
            if (lane == 0) atomicAdd(&g_rtmp[bb * F0 + j0 + jj], v);
        }
    }
}

// ---------------- k4 ----------------
__global__ void k4_norm(float* __restrict__ out) {
    int b = blockIdx.x;
    int j = threadIdx.x;
    float v = g_rtmp[b * F0 + j] * g_s3[j] + g_t3[j];
    __shared__ float red[256];
    red[j] = v * v;
    __syncthreads();
    for (int o = 128; o > 0; o >>= 1) {
        if (j < o) red[j] += red[j + o];
        __syncthreads();
    }
    float nrm = fmaxf(sqrtf(red[0]), 1e-12f);
    out[b * F0 + j] = v / nrm;
}

// ---------------- launch ----------------
extern "C" void kernel_launch(void* const* d_in, const int* in_sizes, int n_in,
                              void* d_out, int out_size) {
    const float* x   = (const float*)d_in[0];
    const int*   len = (const int*)d_in[1];
    const float* w1  = (const float*)d_in[2];
    const float* b1  = (const float*)d_in[3];
    const float* g1  = (const float*)d_in[4];
    const float* be1 = (const float*)d_in[5];
    const float* m1  = (const float*)d_in[6];
    const float* v1  = (const float*)d_in[7];
    const float* w2  = (const float*)d_in[8];
    const float* b2  = (const float*)d_in[9];
    const float* g2  = (const float*)d_in[10];
    const float* be2 = (const float*)d_in[11];
    const float* m2  = (const float*)d_in[12];
    const float* v2  = (const float*)d_in[13];
    const float* fcw = (const float*)d_in[14];
    const float* fcb = (const float*)d_in[15];
    const float* g3  = (const float*)d_in[16];
    const float* be3 = (const float*)d_in[17];
    const float* m3  = (const float*)d_in[18];
    const float* v3  = (const float*)d_in[19];
    float* out = (float*)d_out;

    const int k2_smem = SMEM_FLOATS * 4;  // 227328 B
    cudaFuncSetAttribute(k2_main, cudaFuncAttributeMaxDynamicSharedMemorySize, k2_smem);

    k0_prep<<<1, 1024>>>(len, b1, g1, be1, m1, v1, b2, g2, be2, m2, v2,
                         fcb, g3, be3, m3, v3);
    k0_zero<<<(BSEG * KATT * EPAD + 255) / 256, 256>>>();
    k2_main<<<dim3(NPTS / 128, KATT / TILE_N), 256, k2_smem>>>(x, w1, w2);
    k_out2<<<(BSEG * KC) / 256, 256>>>(len);
    k3_fc<<<128, 256>>>(fcw);
    k4_norm<<<BSEG, 256>>>(out);
}